// round 9
// baseline (speedup 1.0000x reference)
#include <cuda_runtime.h>
#include <cstdint>

#define N_NODES 100000
#define N_EDGES 1600000
#define N_GRAPHS 512
#define FDIM 128
#define SCAN_CHUNK 512
#define SCAN_BLOCKS ((N_NODES + SCAN_CHUNK - 1) / SCAN_CHUNK)   // 196
#define NCHUNK 4

// chunk boundaries (32-aligned)
static const int CH[NCHUNK + 1] = {0, 25024, 50048, 75072, 100000};

// ---------------- device scratch (allocation-free: __device__ globals) ------
__device__ float    g_hA[(size_t)N_NODES * FDIM];
__device__ float    g_hB[(size_t)N_NODES * FDIM];
__device__ float    g_agg[(size_t)N_NODES * FDIM];
__device__ int      g_deg[N_NODES];
__device__ int      g_cursor[N_NODES];
__device__ float    g_dinv[N_NODES];
__device__ int      g_rowoff[N_NODES + 1];
__device__ unsigned long long g_edge[N_EDGES];   // (norm<<32)|src
__device__ int      g_part[SCAN_BLOCKS];
__device__ float    g_sums[N_GRAPHS * FDIM];
__device__ unsigned g_maxenc[N_GRAPHS * FDIM];
__device__ int      g_cnt[N_GRAPHS];

// ---------------- helpers ---------------------------------------------------
__device__ __forceinline__ unsigned enc_max(float f) {
    unsigned u = __float_as_uint(f);
    return (u & 0x80000000u) ? ~u : (u | 0x80000000u);
}
__device__ __forceinline__ float dec_max(unsigned e) {
    unsigned bits = (e & 0x80000000u) ? (e ^ 0x80000000u) : ~e;
    return __uint_as_float(bits);
}

// ---------------- preprocessing ---------------------------------------------
__global__ void zero_kernel() {
    int i = blockIdx.x * blockDim.x + threadIdx.x;
    if (i < N_GRAPHS * FDIM) { g_sums[i] = 0.0f; g_maxenc[i] = 0u; }
    if (i < N_GRAPHS) g_cnt[i] = 0;
    if (i < N_NODES) g_deg[i] = 0;
}

__global__ void hist_kernel(const int* __restrict__ dst) {
    int stride = gridDim.x * blockDim.x;
    for (int e = blockIdx.x * blockDim.x + threadIdx.x; e < N_EDGES; e += stride)
        atomicAdd(&g_deg[dst[e]], 1);
}

__global__ void scan_part() {
    int b = blockIdx.x, t = threadIdx.x;
    int base = b * SCAN_CHUNK;
    int s = 0;
    for (int i = t; i < SCAN_CHUNK; i += 256) {
        int idx = base + i;
        if (idx < N_NODES) s += g_deg[idx];
    }
    __shared__ int sh[8];
#pragma unroll
    for (int o = 16; o; o >>= 1) s += __shfl_down_sync(~0u, s, o);
    if ((t & 31) == 0) sh[t >> 5] = s;
    __syncthreads();
    if (t < 8) {
        int v = sh[t];
#pragma unroll
        for (int o = 4; o; o >>= 1) v += __shfl_down_sync(0xffu, v, o);
        if (t == 0) g_part[b] = v;
    }
}

__global__ void scan_mid() {
    __shared__ int sh[256];
    int t = threadIdx.x;
    int v = (t < SCAN_BLOCKS) ? g_part[t] : 0;
    sh[t] = v;
    __syncthreads();
    for (int o = 1; o < 256; o <<= 1) {
        int u = (t >= o) ? sh[t - o] : 0;
        __syncthreads();
        sh[t] += u;
        __syncthreads();
    }
    if (t < SCAN_BLOCKS) g_part[t] = sh[t] - v;
    if (t == 0) g_rowoff[N_NODES] = N_EDGES;
}

__global__ void scan_final() {
    int b = blockIdx.x, t = threadIdx.x;
    int base = b * SCAN_CHUNK;
    int i0 = base + 2 * t, i1 = i0 + 1;
    int d0 = (i0 < N_NODES) ? g_deg[i0] : 0;
    int d1 = (i1 < N_NODES) ? g_deg[i1] : 0;
    int s = d0 + d1;
    __shared__ int sh[256];
    sh[t] = s;
    __syncthreads();
    for (int o = 1; o < 256; o <<= 1) {
        int u = (t >= o) ? sh[t - o] : 0;
        __syncthreads();
        sh[t] += u;
        __syncthreads();
    }
    int excl = sh[t] - s + g_part[b];
    if (i0 < N_NODES) {
        g_rowoff[i0] = excl;
        g_dinv[i0] = rsqrtf((float)d0 + 1.0f);
        g_cursor[i0] = 0;
    }
    if (i1 < N_NODES) {
        g_rowoff[i1] = excl + d0;
        g_dinv[i1] = rsqrtf((float)d1 + 1.0f);
        g_cursor[i1] = 0;
    }
}

__global__ void scatter_kernel(const int* __restrict__ src, const int* __restrict__ dst) {
    int stride = gridDim.x * blockDim.x;
    for (int e = blockIdx.x * blockDim.x + threadIdx.x; e < N_EDGES; e += stride) {
        int s = src[e], d = dst[e];
        int pos = g_rowoff[d] + atomicAdd(&g_cursor[d], 1);
        float norm = g_dinv[s] * g_dinv[d];
        g_edge[pos] = (unsigned long long)(unsigned)s |
                      ((unsigned long long)__float_as_uint(norm) << 32);
    }
}

// ---------------- dense GEMM (chunked): rows [row_base, ...) ----------------
template <bool RELU_IN>
__global__ void gemm128(const float* __restrict__ A, const float* __restrict__ W,
                        float* __restrict__ out, int row_base) {
    __shared__ float As[32 * 128];
    __shared__ float Ws[32 * 128];
    int tid = threadIdx.x;            // 256 threads
    int row0 = row_base + blockIdx.x * 32;

    const float4* A4 = (const float4*)(A + (size_t)row0 * FDIM);
    float4* As4 = (float4*)As;
#pragma unroll
    for (int i = 0; i < 4; i++) {
        float4 v = A4[tid + i * 256];
        if (RELU_IN) {
            v.x = fmaxf(v.x, 0.0f); v.y = fmaxf(v.y, 0.0f);
            v.z = fmaxf(v.z, 0.0f); v.w = fmaxf(v.w, 0.0f);
        }
        As4[tid + i * 256] = v;
    }

    int warp = tid >> 5, lane = tid & 31;
    float4 acc[4];
#pragma unroll
    for (int r = 0; r < 4; r++) acc[r] = make_float4(0.f, 0.f, 0.f, 0.f);

    for (int kb = 0; kb < 4; kb++) {
        __syncthreads();
        const float4* W4 = (const float4*)(W + (size_t)kb * 32 * FDIM);
        float4* Ws4 = (float4*)Ws;
#pragma unroll
        for (int i = 0; i < 4; i++) Ws4[tid + i * 256] = W4[tid + i * 256];
        __syncthreads();
#pragma unroll
        for (int k = 0; k < 32; k++) {
            float4 w = ((const float4*)Ws)[k * 32 + lane];
#pragma unroll
            for (int r = 0; r < 4; r++) {
                float a = As[(warp * 4 + r) * FDIM + kb * 32 + k];
                acc[r].x += a * w.x; acc[r].y += a * w.y;
                acc[r].z += a * w.z; acc[r].w += a * w.w;
            }
        }
    }
#pragma unroll
    for (int r = 0; r < 4; r++) {
        int row = row0 + warp * 4 + r;
        ((float4*)(out + (size_t)row * FDIM))[lane] = acc[r];
    }
}

// ---------------- aggregation (chunked): warp per dst node ------------------
__global__ void agg_kernel(const float* __restrict__ h, const float* __restrict__ bias,
                           float* __restrict__ out, int node0, int node1) {
    int warpid = (blockIdx.x * blockDim.x + threadIdx.x) >> 5;
    int lane = threadIdx.x & 31;
    int node = node0 + warpid;
    if (node >= node1) return;

    float di = g_dinv[node];
    float sc = di * di;
    float4 b4 = ((const float4*)bias)[lane];
    float4 hv = ((const float4*)(h + (size_t)node * FDIM))[lane];
    float4 acc;
    acc.x = b4.x + hv.x * sc; acc.y = b4.y + hv.y * sc;
    acc.z = b4.z + hv.z * sc; acc.w = b4.w + hv.w * sc;

    int beg = g_rowoff[node];
    int deg = g_rowoff[node + 1] - beg;

    for (int base = 0; base < deg; base += 32) {
        int n = deg - base; if (n > 32) n = 32;
        unsigned lo = 0, hi = 0;
        if (base + lane < deg) {
            unsigned long long e = __ldg(&g_edge[beg + base + lane]);
            lo = (unsigned)e;
            hi = (unsigned)(e >> 32);
        }
#pragma unroll 4
        for (int j = 0; j < n; j++) {
            int s = (int)__shfl_sync(~0u, lo, j);
            float w = __uint_as_float(__shfl_sync(~0u, hi, j));
            float4 v = __ldg((const float4*)(h + (size_t)s * FDIM) + lane);
            acc.x += w * v.x; acc.y += w * v.y;
            acc.z += w * v.z; acc.w += w * v.w;
        }
    }
    ((float4*)(out + (size_t)node * FDIM))[lane] = acc;
}

// ---------------- pooling (chunked): warp per 32 consecutive nodes ----------
__global__ void pool_kernel(const int* __restrict__ batch, int node0, int node1) {
    int warpid = (blockIdx.x * blockDim.x + threadIdx.x) >> 5;
    int lane = threadIdx.x & 31;
    int beg = node0 + warpid * 32;
    if (beg >= node1) return;
    int end = min(beg + 32, node1);

    int cur = batch[beg];
    float4 s = make_float4(0.f, 0.f, 0.f, 0.f);
    float4 m = make_float4(-INFINITY, -INFINITY, -INFINITY, -INFINITY);
    int cnt = 0;

    for (int node = beg; node < end; node++) {
        int b = batch[node];
        if (b != cur) {
            int base = cur * FDIM + lane * 4;
            atomicAdd(&g_sums[base + 0], s.x); atomicAdd(&g_sums[base + 1], s.y);
            atomicAdd(&g_sums[base + 2], s.z); atomicAdd(&g_sums[base + 3], s.w);
            atomicMax(&g_maxenc[base + 0], enc_max(m.x));
            atomicMax(&g_maxenc[base + 1], enc_max(m.y));
            atomicMax(&g_maxenc[base + 2], enc_max(m.z));
            atomicMax(&g_maxenc[base + 3], enc_max(m.w));
            if (lane == 0) atomicAdd(&g_cnt[cur], cnt);
            s = make_float4(0.f, 0.f, 0.f, 0.f);
            m = make_float4(-INFINITY, -INFINITY, -INFINITY, -INFINITY);
            cnt = 0;
            cur = b;
        }
        float4 v = ((const float4*)(g_agg + (size_t)node * FDIM))[lane];
        s.x += v.x; s.y += v.y; s.z += v.z; s.w += v.w;
        m.x = fmaxf(m.x, v.x); m.y = fmaxf(m.y, v.y);
        m.z = fmaxf(m.z, v.z); m.w = fmaxf(m.w, v.w);
        cnt++;
    }
    int base = cur * FDIM + lane * 4;
    atomicAdd(&g_sums[base + 0], s.x); atomicAdd(&g_sums[base + 1], s.y);
    atomicAdd(&g_sums[base + 2], s.z); atomicAdd(&g_sums[base + 3], s.w);
    atomicMax(&g_maxenc[base + 0], enc_max(m.x));
    atomicMax(&g_maxenc[base + 1], enc_max(m.y));
    atomicMax(&g_maxenc[base + 2], enc_max(m.z));
    atomicMax(&g_maxenc[base + 3], enc_max(m.w));
    if (lane == 0) atomicAdd(&g_cnt[cur], cnt);
}

// ---------------- classifier head: one block per graph ----------------------
__global__ void classifier_kernel(const float* __restrict__ Wc1, const float* __restrict__ bc1,
                                  const float* __restrict__ Wc2, const float* __restrict__ bc2,
                                  float* __restrict__ out) {
    int g = blockIdx.x, t = threadIdx.x;  // 128 threads
    __shared__ float gv[256];
    __shared__ float hs[128];

    int cnt = g_cnt[g];
    float inv = 1.0f / (float)max(cnt, 1);
    gv[t] = g_sums[g * FDIM + t] * inv;
    unsigned e = g_maxenc[g * FDIM + t];
    gv[128 + t] = (cnt == 0) ? 0.0f : dec_max(e);
    __syncthreads();

    float acc = bc1[t];
#pragma unroll 8
    for (int k = 0; k < 256; k++) acc += gv[k] * Wc1[k * 128 + t];
    hs[t] = fmaxf(acc, 0.0f);
    __syncthreads();

    if (t < 10) {
        float o = bc2[t];
#pragma unroll 8
        for (int k = 0; k < 128; k++) o += hs[k] * Wc2[k * 10 + t];
        out[g * 10 + t] = o;
    }
}

// ---------------- launch -----------------------------------------------------
static inline int agg_blocks(int n0, int n1) { return ((n1 - n0) * 32 + 255) / 256; }

extern "C" void kernel_launch(void* const* d_in, const int* in_sizes, int n_in,
                              void* d_out, int out_size) {
    const float* x     = (const float*)d_in[0];
    const int*   ei    = (const int*)d_in[1];
    const int*   src   = ei;
    const int*   dst   = ei + N_EDGES;
    const int*   batch = (const int*)d_in[2];
    const float* W1 = (const float*)d_in[3];  const float* b1 = (const float*)d_in[4];
    const float* W2 = (const float*)d_in[5];  const float* b2 = (const float*)d_in[6];
    const float* W3 = (const float*)d_in[7];  const float* b3 = (const float*)d_in[8];
    const float* Wc1 = (const float*)d_in[9]; const float* bc1 = (const float*)d_in[10];
    const float* Wc2 = (const float*)d_in[11]; const float* bc2 = (const float*)d_in[12];
    float* out = (float*)d_out;

    // static side stream + events (created on the uncaptured correctness call)
    static cudaStream_t sB = nullptr;
    static cudaEvent_t evFork, evPre, evG2d, evG3d, evFin;
    static cudaEvent_t evA1[NCHUNK], evA2[NCHUNK], evA3[NCHUNK];
    if (sB == nullptr) {
        cudaStreamCreateWithFlags(&sB, cudaStreamNonBlocking);
        cudaEventCreateWithFlags(&evFork, cudaEventDisableTiming);
        cudaEventCreateWithFlags(&evPre,  cudaEventDisableTiming);
        cudaEventCreateWithFlags(&evG2d,  cudaEventDisableTiming);
        cudaEventCreateWithFlags(&evG3d,  cudaEventDisableTiming);
        cudaEventCreateWithFlags(&evFin,  cudaEventDisableTiming);
        for (int j = 0; j < NCHUNK; j++) {
            cudaEventCreateWithFlags(&evA1[j], cudaEventDisableTiming);
            cudaEventCreateWithFlags(&evA2[j], cudaEventDisableTiming);
            cudaEventCreateWithFlags(&evA3[j], cudaEventDisableTiming);
        }
    }

    float* hA; cudaGetSymbolAddress((void**)&hA, g_hA);
    float* hB; cudaGetSymbolAddress((void**)&hB, g_hB);
    float* ag; cudaGetSymbolAddress((void**)&ag, g_agg);

    // fork: preprocessing on sB concurrent with GEMM1 (full) on main
    cudaEventRecord(evFork, 0);
    cudaStreamWaitEvent(sB, evFork, 0);

    zero_kernel<<<(N_NODES + 255) / 256, 256, 0, sB>>>();
    hist_kernel<<<2048, 256, 0, sB>>>(dst);
    scan_part<<<SCAN_BLOCKS, 256, 0, sB>>>();
    scan_mid<<<1, 256, 0, sB>>>();
    scan_final<<<SCAN_BLOCKS, 256, 0, sB>>>();
    scatter_kernel<<<2048, 256, 0, sB>>>(src, dst);
    cudaEventRecord(evPre, sB);

    gemm128<false><<<N_NODES / 32, 256>>>(x, W1, hA, 0);    // G1 -> hA (full)
    cudaStreamWaitEvent(0, evPre, 0);                       // A1 needs CSR too

    // ---- A1 (reads hA) chunks on main, pipelined with G2 (-> hB) on sB ----
    for (int j = 0; j < NCHUNK; j++) {
        agg_kernel<<<agg_blocks(CH[j], CH[j + 1]), 256>>>(hA, b1, ag, CH[j], CH[j + 1]);
        cudaEventRecord(evA1[j], 0);
        cudaStreamWaitEvent(sB, evA1[j], 0);
        gemm128<true><<<(CH[j + 1] - CH[j]) / 32, 256, 0, sB>>>(ag, W2, hB, CH[j]);
    }
    cudaEventRecord(evG2d, sB);
    cudaStreamWaitEvent(0, evG2d, 0);                       // A2 needs ALL of hB

    // ---- A2 (reads hB) chunks on main, pipelined with G3 (-> hA) on sB ----
    for (int j = 0; j < NCHUNK; j++) {
        agg_kernel<<<agg_blocks(CH[j], CH[j + 1]), 256>>>(hB, b2, ag, CH[j], CH[j + 1]);
        cudaEventRecord(evA2[j], 0);
        cudaStreamWaitEvent(sB, evA2[j], 0);
        gemm128<true><<<(CH[j + 1] - CH[j]) / 32, 256, 0, sB>>>(ag, W3, hA, CH[j]);
    }
    cudaEventRecord(evG3d, sB);
    cudaStreamWaitEvent(0, evG3d, 0);                       // A3 needs ALL of hA

    // ---- A3 (reads hA) chunks on main, pipelined with pool on sB ----
    for (int j = 0; j < NCHUNK; j++) {
        agg_kernel<<<agg_blocks(CH[j], CH[j + 1]), 256>>>(hA, b3, ag, CH[j], CH[j + 1]);
        cudaEventRecord(evA3[j], 0);
        cudaStreamWaitEvent(sB, evA3[j], 0);
        int warps = (CH[j + 1] - CH[j] + 31) / 32;
        pool_kernel<<<(warps * 32 + 255) / 256, 256, 0, sB>>>(batch, CH[j], CH[j + 1]);
    }
    classifier_kernel<<<N_GRAPHS, 128, 0, sB>>>(Wc1, bc1, Wc2, bc2, out);
    cudaEventRecord(evFin, sB);
    cudaStreamWaitEvent(0, evFin, 0);                       // join back to main
}